// round 2
// baseline (speedup 1.0000x reference)
#include <cuda_runtime.h>

#define N_NODES 100000
#define N_EDGES 1600000
#define NFEAT   128
#define NHID    64
#define NCLUS   20

// Scratch (no allocations allowed)
__device__ float g_support[(size_t)N_NODES * NHID];  // x @ W
__device__ float g_dinv[N_NODES];                    // deg -> rsqrt(deg)

// ---------------------------------------------------------------------------
// K1: zero z region of output, init deg to 1.0 (self-loop weight)
// ---------------------------------------------------------------------------
__global__ void k_init(float* __restrict__ z) {
    int t = blockIdx.x * blockDim.x + threadIdx.x;
    if (t < (N_NODES * NHID) / 4)
        ((float4*)z)[t] = make_float4(0.f, 0.f, 0.f, 0.f);
    if (t < N_NODES)
        g_dinv[t] = 1.0f;
}

// ---------------------------------------------------------------------------
// K2: deg[dst] += w[e]   (edge_index is int32, layout [2][E])
// ---------------------------------------------------------------------------
__global__ void k_deg(const int* __restrict__ ei, const float* __restrict__ ew) {
    int e = blockIdx.x * blockDim.x + threadIdx.x;
    if (e >= N_EDGES) return;
    int d = ei[N_EDGES + e];
    atomicAdd(&g_dinv[d], ew[e]);
}

// ---------------------------------------------------------------------------
// K3: dinv = rsqrt(deg)   (deg >= 1 always)
// ---------------------------------------------------------------------------
__global__ void k_rsqrt() {
    int i = blockIdx.x * blockDim.x + threadIdx.x;
    if (i < N_NODES) g_dinv[i] = rsqrtf(g_dinv[i]);
}

// ---------------------------------------------------------------------------
// K4: support = x @ W   (100000x128 @ 128x64)
// Block: 64 rows x 64 cols, 256 threads, 4x4 register tile per thread.
// Dynamic smem: W (128*64 f32) + x tile (64 rows, padded to 132 f32)
// ---------------------------------------------------------------------------
#define GEMM_PAD 132
#define GEMM_SMEM ((NFEAT * NHID + 64 * GEMM_PAD) * 4)

__global__ void k_gemm(const float* __restrict__ x, const float* __restrict__ W) {
    extern __shared__ float sm[];
    float* sW = sm;                    // [128][64]
    float* sX = sm + NFEAT * NHID;     // [64][132]

    int tid  = threadIdx.x;
    int row0 = blockIdx.x * 64;

    // Load W (8192 floats = 2048 float4, 8 per thread)
    {
        const float4* W4 = (const float4*)W;
        float4* sW4 = (float4*)sW;
#pragma unroll
        for (int i = 0; i < 8; i++) sW4[tid + 256 * i] = W4[tid + 256 * i];
    }
    // Load x tile (64 rows x 32 float4)
    for (int i = tid; i < 64 * 32; i += 256) {
        int r = i >> 5, c4 = i & 31;
        int gr = row0 + r;
        float4 v = make_float4(0.f, 0.f, 0.f, 0.f);
        if (gr < N_NODES) v = ((const float4*)(x + (size_t)gr * NFEAT))[c4];
        *(float4*)&sX[r * GEMM_PAD + c4 * 4] = v;
    }
    __syncthreads();

    int ty = tid >> 4;   // 0..15  -> rows ty*4 .. ty*4+3
    int tx = tid & 15;   // 0..15  -> cols tx*4 .. tx*4+3

    float acc[4][4];
#pragma unroll
    for (int i = 0; i < 4; i++)
#pragma unroll
        for (int j = 0; j < 4; j++) acc[i][j] = 0.f;

#pragma unroll 4
    for (int k = 0; k < NFEAT; k++) {
        float4 wv = *(const float4*)&sW[k * NHID + tx * 4];
#pragma unroll
        for (int i = 0; i < 4; i++) {
            float xv = sX[(ty * 4 + i) * GEMM_PAD + k];
            acc[i][0] = fmaf(xv, wv.x, acc[i][0]);
            acc[i][1] = fmaf(xv, wv.y, acc[i][1]);
            acc[i][2] = fmaf(xv, wv.z, acc[i][2]);
            acc[i][3] = fmaf(xv, wv.w, acc[i][3]);
        }
    }

#pragma unroll
    for (int i = 0; i < 4; i++) {
        int gr = row0 + ty * 4 + i;
        if (gr < N_NODES)
            *(float4*)&g_support[(size_t)gr * NHID + tx * 4] =
                make_float4(acc[i][0], acc[i][1], acc[i][2], acc[i][3]);
    }
}

// ---------------------------------------------------------------------------
// K5: scatter  z[dst] += support[src] * (dinv[src]*w*dinv[dst])
// 16 threads per edge, one float4 + red.global.add.v4.f32 each.
// ---------------------------------------------------------------------------
__global__ void k_scatter(const int* __restrict__ ei,
                          const float* __restrict__ ew,
                          float* __restrict__ z) {
    long long t = (long long)blockIdx.x * blockDim.x + threadIdx.x;
    int e = (int)(t >> 4);
    if (e >= N_EDGES) return;
    int c = (int)(t & 15) << 2;

    int s = ei[e];
    int d = ei[N_EDGES + e];
    float nrm = g_dinv[s] * ew[e] * g_dinv[d];

    float4 v = *(const float4*)(g_support + (size_t)s * NHID + c);
    float* p = z + (size_t)d * NHID + c;
    asm volatile("red.global.add.v4.f32 [%0], {%1, %2, %3, %4};"
                 :: "l"(p), "f"(v.x * nrm), "f"(v.y * nrm),
                    "f"(v.z * nrm), "f"(v.w * nrm)
                 : "memory");
}

// ---------------------------------------------------------------------------
// K6: finalize z (self-loop + bias) and compute Student-t q
// One thread per node; z row in registers; mu/b in smem.
// ---------------------------------------------------------------------------
__global__ void k_final(const float* __restrict__ b,
                        const float* __restrict__ mu,
                        float* __restrict__ out) {
    __shared__ float smu[NCLUS * NHID];
    __shared__ float sb[NHID];
    int tid = threadIdx.x;
    for (int i = tid; i < NCLUS * NHID; i += blockDim.x) smu[i] = mu[i];
    if (tid < NHID) sb[tid] = b[tid];
    __syncthreads();

    int i = blockIdx.x * blockDim.x + tid;
    if (i >= N_NODES) return;

    float di = g_dinv[i];
    float sl = di * di;   // self-loop norm (weight 1)

    float zv[NHID];
    float4* zp = (float4*)(out + (size_t)i * NHID);
    const float4* sp = (const float4*)(g_support + (size_t)i * NHID);
#pragma unroll
    for (int j = 0; j < NHID / 4; j++) {
        float4 a = zp[j];
        float4 s = sp[j];
        zv[4 * j + 0] = a.x + s.x * sl + sb[4 * j + 0];
        zv[4 * j + 1] = a.y + s.y * sl + sb[4 * j + 1];
        zv[4 * j + 2] = a.z + s.z * sl + sb[4 * j + 2];
        zv[4 * j + 3] = a.w + s.w * sl + sb[4 * j + 3];
        zp[j] = make_float4(zv[4 * j + 0], zv[4 * j + 1], zv[4 * j + 2], zv[4 * j + 3]);
    }

    float d2[NCLUS];
#pragma unroll
    for (int k = 0; k < NCLUS; k++) d2[k] = 0.f;

#pragma unroll 4
    for (int h = 0; h < NHID; h++) {
        float zh = zv[h];
#pragma unroll
        for (int k = 0; k < NCLUS; k++) {
            float df = zh - smu[k * NHID + h];
            d2[k] = fmaf(df, df, d2[k]);
        }
    }

    float p[NCLUS];
    float sum = 0.f;
#pragma unroll
    for (int k = 0; k < NCLUS; k++) {
        float q = 1.f / (1.f + d2[k] * 5.0f + 1e-8f);   // d2/ALPHA, ALPHA=0.2
        float v = 0.5f * powf(q, 1.2f);                 // q^(alpha+1) / 2
        p[k] = v;
        sum += v;
    }
    float inv = 1.f / sum;
    float* qo = out + (size_t)N_NODES * NHID + (size_t)i * NCLUS;
#pragma unroll
    for (int k = 0; k < NCLUS; k++) qo[k] = p[k] * inv;
}

// ---------------------------------------------------------------------------
extern "C" void kernel_launch(void* const* d_in, const int* in_sizes, int n_in,
                              void* d_out, int out_size) {
    const float* x  = (const float*)d_in[0];
    const int*   ei = (const int*)d_in[1];
    const float* ew = (const float*)d_in[2];
    const float* W  = (const float*)d_in[3];
    const float* b  = (const float*)d_in[4];
    const float* mu = (const float*)d_in[5];
    float* out = (float*)d_out;

    cudaFuncSetAttribute(k_gemm, cudaFuncAttributeMaxDynamicSharedMemorySize, GEMM_SMEM);

    {   // zero z + init deg
        int n = (N_NODES * NHID) / 4;
        k_init<<<(n + 255) / 256, 256>>>(out);
    }
    k_deg<<<(N_EDGES + 255) / 256, 256>>>(ei, ew);
    k_rsqrt<<<(N_NODES + 255) / 256, 256>>>();
    k_gemm<<<(N_NODES + 63) / 64, 256, GEMM_SMEM>>>(x, W);
    {   // 16 threads per edge
        long long tot = (long long)N_EDGES * 16;
        int blocks = (int)((tot + 255) / 256);
        k_scatter<<<blocks, 256>>>(ei, ew, out);
    }
    k_final<<<(N_NODES + 255) / 256, 256>>>(b, mu, out);
}

// round 3
// speedup vs baseline: 1.4435x; 1.4435x over previous
#include <cuda_runtime.h>

#define N_NODES 100000
#define N_EDGES 1600000
#define NFEAT   128
#define NHID    64
#define NCLUS   20
#define NBLK_SCAN 98   // ceil(100000/1024)

// ---------------- scratch (static device globals; no allocation) -----------
__device__ float              g_support[(size_t)N_NODES * NHID]; // x @ W
__device__ float              g_dinv[N_NODES];                   // rsqrt(deg)
__device__ int                g_count[N_NODES];                  // in-degree
__device__ int                g_off[N_NODES];                    // CSR offsets (excl)
__device__ int                g_cur[N_NODES];                    // bin cursors
__device__ int                g_bsum[NBLK_SCAN];                 // scan partials
__device__ int                g_boff[NBLK_SCAN];
__device__ unsigned long long g_edges[N_EDGES];                  // packed (norm<<32)|src

// packed f32x2 FMA: d = a*b + d  (both lanes)
__device__ __forceinline__ void ffma2(float2& d, const float2 a, const float2 b) {
    asm("fma.rn.f32x2 %0, %1, %2, %0;"
        : "+l"(*(unsigned long long*)&d)
        : "l"(*(const unsigned long long*)&a),
          "l"(*(const unsigned long long*)&b));
}

// ---------------------------------------------------------------------------
// K1: deg = 1 (self loop), count = 0
// ---------------------------------------------------------------------------
__global__ void k_init() {
    int i = blockIdx.x * blockDim.x + threadIdx.x;
    if (i < N_NODES) { g_dinv[i] = 1.0f; g_count[i] = 0; }
}

// ---------------------------------------------------------------------------
// K2: deg[dst] += w;  count[dst]++
// ---------------------------------------------------------------------------
__global__ void k_deg(const int* __restrict__ ei, const float* __restrict__ ew) {
    int e = blockIdx.x * blockDim.x + threadIdx.x;
    if (e >= N_EDGES) return;
    int d = ei[N_EDGES + e];
    atomicAdd(&g_dinv[d], ew[e]);
    atomicAdd(&g_count[d], 1);
}

// ---------------------------------------------------------------------------
// K3: dinv = rsqrt(deg)
// ---------------------------------------------------------------------------
__global__ void k_rsqrt() {
    int i = blockIdx.x * blockDim.x + threadIdx.x;
    if (i < N_NODES) g_dinv[i] = rsqrtf(g_dinv[i]);
}

// ---------------------------------------------------------------------------
// K4a/b/c: exclusive scan of g_count -> g_off (3-phase block scan)
// ---------------------------------------------------------------------------
__global__ void k_scan1() {
    __shared__ int sm[1024];
    int i = blockIdx.x * 1024 + threadIdx.x;
    int v = (i < N_NODES) ? g_count[i] : 0;
    sm[threadIdx.x] = v;
    __syncthreads();
    for (int off = 1; off < 1024; off <<= 1) {
        int t = (threadIdx.x >= off) ? sm[threadIdx.x - off] : 0;
        __syncthreads();
        sm[threadIdx.x] += t;
        __syncthreads();
    }
    if (i < N_NODES) g_off[i] = sm[threadIdx.x] - v;      // exclusive
    if (threadIdx.x == 1023) g_bsum[blockIdx.x] = sm[1023];
}

__global__ void k_scan2() {
    __shared__ int sm[128];
    int t = threadIdx.x;
    int v = (t < NBLK_SCAN) ? g_bsum[t] : 0;
    sm[t] = v;
    __syncthreads();
    for (int off = 1; off < 128; off <<= 1) {
        int u = (t >= off) ? sm[t - off] : 0;
        __syncthreads();
        sm[t] += u;
        __syncthreads();
    }
    if (t < NBLK_SCAN) g_boff[t] = sm[t] - v;             // exclusive
}

__global__ void k_scan3() {
    int i = blockIdx.x * 1024 + threadIdx.x;
    if (i < N_NODES) {
        int o = g_off[i] + g_boff[blockIdx.x];
        g_off[i] = o;
        g_cur[i] = o;
    }
}

// ---------------------------------------------------------------------------
// K5: bin-fill — place (src, norm) of each edge into its dst bin
// ---------------------------------------------------------------------------
__global__ void k_binfill(const int* __restrict__ ei, const float* __restrict__ ew) {
    int e = blockIdx.x * blockDim.x + threadIdx.x;
    if (e >= N_EDGES) return;
    int s = ei[e];
    int d = ei[N_EDGES + e];
    float nrm = g_dinv[s] * ew[e] * g_dinv[d];
    int pos = atomicAdd(&g_cur[d], 1);
    g_edges[pos] = ((unsigned long long)__float_as_uint(nrm) << 32) | (unsigned)s;
}

// ---------------------------------------------------------------------------
// K6: support = x @ W  (100000x128 @ 128x64)
// 128-row x 64-col block, 256 threads, 4x8 thread tile, packed f32x2 FMA.
// ---------------------------------------------------------------------------
#define GEMM_ROWS 128
#define GEMM_PAD  132
#define GEMM_SMEM ((NFEAT * NHID + GEMM_ROWS * GEMM_PAD) * 4)

__global__ void k_gemm(const float* __restrict__ x, const float* __restrict__ W) {
    extern __shared__ float sm[];
    float* sW = sm;                    // [128][64]
    float* sX = sm + NFEAT * NHID;     // [128][132]

    int tid  = threadIdx.x;
    int row0 = blockIdx.x * GEMM_ROWS;

    {   // W: 8192 floats = 2048 float4
        const float4* W4 = (const float4*)W;
        float4* sW4 = (float4*)sW;
#pragma unroll
        for (int i = 0; i < 8; i++) sW4[tid + 256 * i] = W4[tid + 256 * i];
    }
    // x tile: 128 rows x 32 float4
    for (int i = tid; i < GEMM_ROWS * 32; i += 256) {
        int r = i >> 5, c4 = i & 31;
        int gr = row0 + r;
        float4 v = make_float4(0.f, 0.f, 0.f, 0.f);
        if (gr < N_NODES) v = ((const float4*)(x + (size_t)gr * NFEAT))[c4];
        *(float4*)&sX[r * GEMM_PAD + c4 * 4] = v;
    }
    __syncthreads();

    int ty = tid >> 3;   // 0..31 -> rows ty*4..+3
    int tx = tid & 7;    // 0..7  -> cols tx*8..+7

    float2 acc[4][4];
#pragma unroll
    for (int i = 0; i < 4; i++)
#pragma unroll
        for (int c = 0; c < 4; c++) acc[i][c] = make_float2(0.f, 0.f);

#pragma unroll 4
    for (int k = 0; k < NFEAT; k++) {
        float4 w01 = *(const float4*)&sW[k * NHID + tx * 8];
        float4 w23 = *(const float4*)&sW[k * NHID + tx * 8 + 4];
        float2 wv[4] = { make_float2(w01.x, w01.y), make_float2(w01.z, w01.w),
                         make_float2(w23.x, w23.y), make_float2(w23.z, w23.w) };
#pragma unroll
        for (int i = 0; i < 4; i++) {
            float xv = sX[(ty * 4 + i) * GEMM_PAD + k];
            float2 xx = make_float2(xv, xv);
#pragma unroll
            for (int c = 0; c < 4; c++) ffma2(acc[i][c], xx, wv[c]);
        }
    }

#pragma unroll
    for (int i = 0; i < 4; i++) {
        int gr = row0 + ty * 4 + i;
        if (gr < N_NODES) {
            float* p = g_support + (size_t)gr * NHID + tx * 8;
            *(float4*)p       = make_float4(acc[i][0].x, acc[i][0].y, acc[i][1].x, acc[i][1].y);
            *(float4*)(p + 4) = make_float4(acc[i][2].x, acc[i][2].y, acc[i][3].x, acc[i][3].y);
        }
    }
}

// ---------------------------------------------------------------------------
// K7: gather — one warp per node.
// z[i] = b + dinv[i]^2 * support[i] + sum_e norm_e * support[src_e]
// Each lane owns 2 columns (float2). No atomics.
// ---------------------------------------------------------------------------
__global__ void k_gather(const float* __restrict__ b, float* __restrict__ out) {
    int wid  = (blockIdx.x * blockDim.x + threadIdx.x) >> 5;
    int lane = threadIdx.x & 31;
    if (wid >= N_NODES) return;

    int beg = g_off[wid];
    int cnt = g_count[wid];

    float di = g_dinv[wid];
    float sl = di * di;
    float2 sls = make_float2(sl, sl);

    float2 acc = *(const float2*)(b + 2 * lane);
    float2 sv  = *(const float2*)(g_support + (size_t)wid * NHID + 2 * lane);
    ffma2(acc, sls, sv);

    for (int base = 0; base < cnt; base += 32) {
        int rem = cnt - base;
        int chunk = rem < 32 ? rem : 32;
        unsigned long long pk = 0;
        if (lane < chunk) pk = g_edges[beg + base + lane];
#pragma unroll 4
        for (int j = 0; j < chunk; j++) {
            unsigned long long pj = __shfl_sync(0xFFFFFFFFu, pk, j);
            int   s = (int)(unsigned)pj;
            float n = __uint_as_float((unsigned)(pj >> 32));
            float2 nn = make_float2(n, n);
            float2 v = *(const float2*)(g_support + (size_t)s * NHID + 2 * lane);
            ffma2(acc, nn, v);
        }
    }

    *(float2*)(out + (size_t)wid * NHID + 2 * lane) = acc;
}

// ---------------------------------------------------------------------------
// K8: Student-t soft assignment q from z
// ---------------------------------------------------------------------------
__global__ void k_q(const float* __restrict__ mu, float* __restrict__ out) {
    __shared__ float smu[NCLUS * NHID];
    int tid = threadIdx.x;
    for (int i = tid; i < NCLUS * NHID; i += blockDim.x) smu[i] = mu[i];
    __syncthreads();

    int i = blockIdx.x * blockDim.x + tid;
    if (i >= N_NODES) return;

    float zv[NHID];
    const float4* zp = (const float4*)(out + (size_t)i * NHID);
#pragma unroll
    for (int j = 0; j < NHID / 4; j++) {
        float4 a = zp[j];
        zv[4 * j + 0] = a.x; zv[4 * j + 1] = a.y;
        zv[4 * j + 2] = a.z; zv[4 * j + 3] = a.w;
    }

    float d2[NCLUS];
#pragma unroll
    for (int k = 0; k < NCLUS; k++) d2[k] = 0.f;

#pragma unroll
    for (int h = 0; h < NHID; h++) {
        float zh = zv[h];
#pragma unroll
        for (int k = 0; k < NCLUS; k++) {
            float df = zh - smu[k * NHID + h];
            d2[k] = fmaf(df, df, d2[k]);
        }
    }

    float p[NCLUS];
    float sum = 0.f;
#pragma unroll
    for (int k = 0; k < NCLUS; k++) {
        float q = 1.f / (1.f + d2[k] * 5.0f + 1e-8f);   // d2/ALPHA, ALPHA=0.2
        float v = 0.5f * powf(q, 1.2f);                 // q^(alpha+1) / 2
        p[k] = v;
        sum += v;
    }
    float inv = 1.f / sum;
    float* qo = out + (size_t)N_NODES * NHID + (size_t)i * NCLUS;
#pragma unroll
    for (int k = 0; k < NCLUS; k++) qo[k] = p[k] * inv;
}

// ---------------------------------------------------------------------------
extern "C" void kernel_launch(void* const* d_in, const int* in_sizes, int n_in,
                              void* d_out, int out_size) {
    const float* x  = (const float*)d_in[0];
    const int*   ei = (const int*)d_in[1];
    const float* ew = (const float*)d_in[2];
    const float* W  = (const float*)d_in[3];
    const float* b  = (const float*)d_in[4];
    const float* mu = (const float*)d_in[5];
    float* out = (float*)d_out;

    cudaFuncSetAttribute(k_gemm, cudaFuncAttributeMaxDynamicSharedMemorySize, GEMM_SMEM);

    k_init<<<(N_NODES + 255) / 256, 256>>>();
    k_deg<<<(N_EDGES + 255) / 256, 256>>>(ei, ew);
    k_rsqrt<<<(N_NODES + 255) / 256, 256>>>();
    k_scan1<<<NBLK_SCAN, 1024>>>();
    k_scan2<<<1, 128>>>();
    k_scan3<<<NBLK_SCAN, 1024>>>();
    k_binfill<<<(N_EDGES + 255) / 256, 256>>>(ei, ew);
    k_gemm<<<(N_NODES + GEMM_ROWS - 1) / GEMM_ROWS, 256, GEMM_SMEM>>>(x, W);
    k_gather<<<(N_NODES * 32 + 255) / 256, 256>>>(b, out);
    k_q<<<(N_NODES + 255) / 256, 256>>>(mu, out);
}